// round 1
// baseline (speedup 1.0000x reference)
#include <cuda_runtime.h>
#include <math.h>

#define D_MODEL 512
#define HEADS   8
#define HDIM    64
#define NSEQ    1024
#define TOPK    102
#define MAXM    2048   // B*N for B=2

// ---------------- scratch (static device globals; no allocs) ----------------
__device__ float g_QKV[3u * MAXM * D_MODEL];   // Q | K | V, each [M,512]
__device__ float g_att[MAXM * D_MODEL];        // attention output pre-Wo
__device__ unsigned char g_qh[MAXM * HEADS];   // [(b*8+h)*1024 + n]
__device__ unsigned char g_kh[MAXM * HEADS];

// ---------------- SGEMM: C = A[M,512] * W[512,512]^T ----------------
#define BM 64
#define BN 128
#define BK 16
#define TM 4
#define TN 8

__global__ __launch_bounds__(256) void gemm_qkv_kernel(
    const float* __restrict__ A,
    const float* __restrict__ Wq, const float* __restrict__ Wk,
    const float* __restrict__ Wv, int M)
{
    __shared__ __align__(16) float As[BK][BM];
    __shared__ __align__(16) float Bs[BK][BN];

    int gn    = blockIdx.y * BN;            // global out col in [0,1536)
    int which = gn >> 9;                    // 0:Q 1:K 2:V
    int bn    = gn & 511;
    const float* W = (which == 0) ? Wq : (which == 1) ? Wk : Wv;
    float* C = g_QKV + (size_t)which * M * D_MODEL;

    int bm  = blockIdx.x * BM;
    int tid = threadIdx.x;
    int trow = tid >> 4;        // 0..15 -> m block
    int tcol = tid & 15;        // 0..15 -> n block
    float acc[TM][TN] = {};

    int ar = tid >> 2;          // 0..63
    int ac = (tid & 3) << 2;    // 0,4,8,12

    for (int k0 = 0; k0 < D_MODEL; k0 += BK) {
        float4 av = *reinterpret_cast<const float4*>(&A[(size_t)(bm + ar) * D_MODEL + k0 + ac]);
        As[ac + 0][ar] = av.x; As[ac + 1][ar] = av.y;
        As[ac + 2][ar] = av.z; As[ac + 3][ar] = av.w;
#pragma unroll
        for (int p = 0; p < 2; ++p) {
            float4 wv4 = *reinterpret_cast<const float4*>(&W[(size_t)(bn + ar + p * 64) * D_MODEL + k0 + ac]);
            Bs[ac + 0][ar + p * 64] = wv4.x; Bs[ac + 1][ar + p * 64] = wv4.y;
            Bs[ac + 2][ar + p * 64] = wv4.z; Bs[ac + 3][ar + p * 64] = wv4.w;
        }
        __syncthreads();
#pragma unroll
        for (int k = 0; k < BK; ++k) {
            float4 a4 = *reinterpret_cast<const float4*>(&As[k][trow * TM]);
            float4 b0 = *reinterpret_cast<const float4*>(&Bs[k][tcol * TN]);
            float4 b1 = *reinterpret_cast<const float4*>(&Bs[k][tcol * TN + 4]);
            float aR[TM] = {a4.x, a4.y, a4.z, a4.w};
            float bR[TN] = {b0.x, b0.y, b0.z, b0.w, b1.x, b1.y, b1.z, b1.w};
#pragma unroll
            for (int i = 0; i < TM; ++i)
#pragma unroll
                for (int j = 0; j < TN; ++j)
                    acc[i][j] = fmaf(aR[i], bR[j], acc[i][j]);
        }
        __syncthreads();
    }
#pragma unroll
    for (int i = 0; i < TM; ++i) {
        float4* dst = reinterpret_cast<float4*>(&C[(size_t)(bm + trow * TM + i) * D_MODEL + bn + tcol * TN]);
        dst[0] = make_float4(acc[i][0], acc[i][1], acc[i][2], acc[i][3]);
        dst[1] = make_float4(acc[i][4], acc[i][5], acc[i][6], acc[i][7]);
    }
}

__global__ __launch_bounds__(256) void gemm_o_kernel(
    const float* __restrict__ Wo, float* __restrict__ Cout, int M)
{
    __shared__ __align__(16) float As[BK][BM];
    __shared__ __align__(16) float Bs[BK][BN];

    const float* A = g_att;
    int bn = blockIdx.y * BN;
    int bm = blockIdx.x * BM;
    int tid = threadIdx.x;
    int trow = tid >> 4;
    int tcol = tid & 15;
    float acc[TM][TN] = {};
    int ar = tid >> 2;
    int ac = (tid & 3) << 2;

    for (int k0 = 0; k0 < D_MODEL; k0 += BK) {
        float4 av = *reinterpret_cast<const float4*>(&A[(size_t)(bm + ar) * D_MODEL + k0 + ac]);
        As[ac + 0][ar] = av.x; As[ac + 1][ar] = av.y;
        As[ac + 2][ar] = av.z; As[ac + 3][ar] = av.w;
#pragma unroll
        for (int p = 0; p < 2; ++p) {
            float4 wv4 = *reinterpret_cast<const float4*>(&Wo[(size_t)(bn + ar + p * 64) * D_MODEL + k0 + ac]);
            Bs[ac + 0][ar + p * 64] = wv4.x; Bs[ac + 1][ar + p * 64] = wv4.y;
            Bs[ac + 2][ar + p * 64] = wv4.z; Bs[ac + 3][ar + p * 64] = wv4.w;
        }
        __syncthreads();
#pragma unroll
        for (int k = 0; k < BK; ++k) {
            float4 a4 = *reinterpret_cast<const float4*>(&As[k][trow * TM]);
            float4 b0 = *reinterpret_cast<const float4*>(&Bs[k][tcol * TN]);
            float4 b1 = *reinterpret_cast<const float4*>(&Bs[k][tcol * TN + 4]);
            float aR[TM] = {a4.x, a4.y, a4.z, a4.w};
            float bR[TN] = {b0.x, b0.y, b0.z, b0.w, b1.x, b1.y, b1.z, b1.w};
#pragma unroll
            for (int i = 0; i < TM; ++i)
#pragma unroll
                for (int j = 0; j < TN; ++j)
                    acc[i][j] = fmaf(aR[i], bR[j], acc[i][j]);
        }
        __syncthreads();
    }
#pragma unroll
    for (int i = 0; i < TM; ++i) {
        float4* dst = reinterpret_cast<float4*>(&Cout[(size_t)(bm + trow * TM + i) * D_MODEL + bn + tcol * TN]);
        dst[0] = make_float4(acc[i][0], acc[i][1], acc[i][2], acc[i][3]);
        dst[1] = make_float4(acc[i][4], acc[i][5], acc[i][6], acc[i][7]);
    }
}

// ---------------- LSH hashes ----------------
__global__ __launch_bounds__(256) void hash_kernel(const float* __restrict__ rv, int M)
{
    __shared__ float rs[HEADS * HDIM];
    for (int i = threadIdx.x; i < HEADS * HDIM; i += blockDim.x) rs[i] = rv[i];
    __syncthreads();

    int idx = blockIdx.x * blockDim.x + threadIdx.x;
    int total = 2 * M * HEADS;
    if (idx >= total) return;
    int isK = (idx >= M * HEADS) ? 1 : 0;
    int r = idx - isK * M * HEADS;
    int row = r >> 3;        // 0..M-1 (= b*1024+n)
    int h   = r & 7;

    const float* src = g_QKV + (size_t)isK * M * D_MODEL + (size_t)row * D_MODEL + h * HDIM;
    float dacc[8] = {};
#pragma unroll 8
    for (int c = 0; c < HDIM; ++c) {
        float x = src[c];
#pragma unroll
        for (int k = 0; k < 8; ++k) dacc[k] = fmaf(x, rs[k * HDIM + c], dacc[k]);
    }
    unsigned int bits = 0;
#pragma unroll
    for (int k = 0; k < 8; ++k) bits |= (dacc[k] >= 0.f ? 1u : 0u) << k;
    int bhn = ((row >> 10) * HEADS + h) * NSEQ + (row & (NSEQ - 1));
    (isK ? g_kh : g_qh)[bhn] = (unsigned char)bits;
}

// ---------------- sparse hyperbolic attention: one block per (b,h,n) ----------------
__global__ __launch_bounds__(128) void attn_kernel(int M)
{
    const int T = 128;
    int gid = blockIdx.x;                // bh*1024 + n
    int n  = gid & (NSEQ - 1);
    int bh = gid >> 10;
    int h = bh & 7, b = bh >> 3;

    const float* Q = g_QKV;
    const float* K = g_QKV + (size_t)M * D_MODEL;
    const float* V = g_QKV + 2 * (size_t)M * D_MODEL;

    __shared__ float qs[HDIM];
    __shared__ float sc[TOPK];
    __shared__ short selj[TOPK];
    __shared__ unsigned char mt[NSEQ];
    __shared__ int hist[9];
    __shared__ int scanbuf[T];
    __shared__ int s_t, s_need, s_cnt;
    __shared__ float s_qn, s_mx, s_sum;
    __shared__ float red[4];
    __shared__ float obuf[HDIM];

    int tid = threadIdx.x;
    size_t qoff = ((size_t)(b * NSEQ + n)) * D_MODEL + h * HDIM;
    if (tid < HDIM) qs[tid] = Q[qoff + tid];
    if (tid < 9) hist[tid] = 0;
    if (tid == 0) s_cnt = 0;
    __syncthreads();

    unsigned int qb = g_qh[bh * NSEQ + n];
    const unsigned char* khb = g_kh + bh * NSEQ;
#pragma unroll
    for (int j = tid; j < NSEQ; j += T) {
        int m = 8 - __popc((qb ^ (unsigned int)khb[j]) & 0xFFu);
        mt[j] = (unsigned char)m;
        atomicAdd(&hist[m], 1);
    }
    // q norm (qs is safe: synced above)
    if (tid < 32) {
        float v = qs[tid] * qs[tid] + qs[tid + 32] * qs[tid + 32];
#pragma unroll
        for (int o = 16; o > 0; o >>= 1) v += __shfl_xor_sync(0xffffffffu, v, o);
        if (tid == 0) s_qn = v;
    }
    __syncthreads();

    if (tid == 0) {
        int cum = 0, t = 0, need = TOPK;
        for (int v = 8; v >= 0; --v) {
            if (cum + hist[v] >= TOPK) { t = v; need = TOPK - cum; break; }
            cum += hist[v];
        }
        s_t = t; s_need = need;
    }
    __syncthreads();
    int t = s_t, need = s_need;

    // ascending-index tie-break: rank of ==t keys via segment counts + scan
    int base = tid * (NSEQ / T);
    int cnteq = 0;
#pragma unroll
    for (int i = 0; i < NSEQ / T; ++i) cnteq += (mt[base + i] == t);
    scanbuf[tid] = cnteq;
    __syncthreads();
    if (tid == 0) {
        int acc2 = 0;
        for (int i = 0; i < T; ++i) { int c = scanbuf[i]; scanbuf[i] = acc2; acc2 += c; }
    }
    __syncthreads();
    int rank = scanbuf[tid];
#pragma unroll
    for (int i = 0; i < NSEQ / T; ++i) {
        int j = base + i;
        int m = mt[j];
        bool sel = (m > t) || (m == t && rank < need);
        rank += (m == t);
        if (sel) { int p = atomicAdd(&s_cnt, 1); selj[p] = (short)j; }
    }
    __syncthreads();

    // Poincare distances for the 102 selected keys
    float qn = s_qn;
    for (int s = tid; s < TOPK; s += T) {
        int j = selj[s];
        const float* kr = K + ((size_t)(b * NSEQ + j)) * D_MODEL + h * HDIM;
        float dsq = 0.f, kn = 0.f;
#pragma unroll
        for (int d0 = 0; d0 < HDIM; d0 += 4) {
            float4 kv = *reinterpret_cast<const float4*>(kr + d0);
            float dx = qs[d0 + 0] - kv.x, dy = qs[d0 + 1] - kv.y;
            float dz = qs[d0 + 2] - kv.z, dw = qs[d0 + 3] - kv.w;
            dsq += dx * dx + dy * dy + dz * dz + dw * dw;
            kn  += kv.x * kv.x + kv.y * kv.y + kv.z * kv.z + kv.w * kv.w;
        }
        float denom = fmaxf((1.f - qn) * (1.f - kn), 1e-6f);
        float ca = fmaxf(1.f + 2.f * dsq / denom, 1.f);
        sc[s] = -acoshf(ca);
    }
    __syncthreads();

    // softmax over 102 scores
    {
        float v = (tid < TOPK) ? sc[tid] : -3.4e38f;
#pragma unroll
        for (int o = 16; o > 0; o >>= 1) v = fmaxf(v, __shfl_xor_sync(0xffffffffu, v, o));
        if ((tid & 31) == 0) red[tid >> 5] = v;
        __syncthreads();
        if (tid == 0) s_mx = fmaxf(fmaxf(red[0], red[1]), fmaxf(red[2], red[3]));
        __syncthreads();
        float e = (tid < TOPK) ? expf(sc[tid] - s_mx) : 0.f;
        if (tid < TOPK) sc[tid] = e;
        float sv = e;
#pragma unroll
        for (int o = 16; o > 0; o >>= 1) sv += __shfl_xor_sync(0xffffffffu, sv, o);
        if ((tid & 31) == 0) red[tid >> 5] = sv;
        __syncthreads();
        if (tid == 0) s_sum = red[0] + red[1] + red[2] + red[3];
        __syncthreads();
    }
    float inv = 1.f / s_sum;

    // out[d] = (sum_s e_s * V[j_s, d]) / sum; split s-range across the two halves
    int d = tid & (HDIM - 1);
    int half = tid >> 6;
    float acc = 0.f;
    int s0 = half ? 51 : 0;
    int s1 = half ? TOPK : 51;
    for (int s = s0; s < s1; ++s) {
        int j = selj[s];
        acc += sc[s] * V[((size_t)(b * NSEQ + j)) * D_MODEL + h * HDIM + d];
    }
    if (half == 0) obuf[d] = acc;
    __syncthreads();
    if (half == 1)
        g_att[((size_t)(b * NSEQ + n)) * D_MODEL + h * HDIM + d] = (obuf[d] + acc) * inv;
}

// ---------------- entry ----------------
extern "C" void kernel_launch(void* const* d_in, const int* in_sizes, int n_in,
                              void* d_out, int out_size)
{
    const float* x  = (const float*)d_in[0];
    const float* Wq = (const float*)d_in[1];
    const float* Wk = (const float*)d_in[2];
    const float* Wv = (const float*)d_in[3];
    const float* Wo = (const float*)d_in[4];
    const float* rv = (const float*)d_in[5];
    float* out = (float*)d_out;

    int M = in_sizes[0] / D_MODEL;   // B*N = 2048

    dim3 gq(M / BM, (3 * D_MODEL) / BN);      // (32, 12)
    gemm_qkv_kernel<<<gq, 256>>>(x, Wq, Wk, Wv, M);

    int hthreads = 2 * M * HEADS;             // 32768
    hash_kernel<<<(hthreads + 255) / 256, 256>>>(rv, M);

    attn_kernel<<<M * HEADS, 128>>>(M);       // 16384 blocks

    dim3 go(M / BM, D_MODEL / BN);            // (32, 4)
    gemm_o_kernel<<<go, 256>>>(Wo, out, M);
}

// round 2
// speedup vs baseline: 1.1403x; 1.1403x over previous
#include <cuda_runtime.h>
#include <math.h>

#define D_MODEL 512
#define HEADS   8
#define HDIM    64
#define NSEQ    1024
#define TOPK    102
#define MAXM    2048   // B*N for B=2

// ---------------- scratch (static device globals; no allocs) ----------------
__device__ float g_QKV[3u * MAXM * D_MODEL];   // Q | K | V, each [M,512]
__device__ float g_att[MAXM * D_MODEL];        // attention output pre-Wo
__device__ unsigned char g_qh[MAXM * HEADS];   // [(b*8+h)*1024 + n]
__device__ unsigned char g_kh[MAXM * HEADS];

// ---------------- SGEMM: C = A[M,512] * W[512,512]^T, 64x64 tiles ----------------
#define BM 64
#define BN 64
#define BK 16

__device__ __forceinline__ void gemm_body(
    const float* __restrict__ A, const float* __restrict__ W,
    float* __restrict__ C, int bm, int bn)
{
    __shared__ __align__(16) float As[BK][BM];
    __shared__ __align__(16) float Bs[BK][BN];

    int tid  = threadIdx.x;
    int trow = tid >> 4;        // 0..15
    int tcol = tid & 15;        // 0..15
    int lrow = tid >> 2;        // 0..63 (load row)
    int lkc  = (tid & 3) << 2;  // 0,4,8,12 (load k offset)
    float acc[4][4] = {};

    for (int k0 = 0; k0 < D_MODEL; k0 += BK) {
        float4 av = *reinterpret_cast<const float4*>(&A[(size_t)(bm + lrow) * D_MODEL + k0 + lkc]);
        float4 wv = *reinterpret_cast<const float4*>(&W[(size_t)(bn + lrow) * D_MODEL + k0 + lkc]);
        As[lkc + 0][lrow] = av.x; As[lkc + 1][lrow] = av.y;
        As[lkc + 2][lrow] = av.z; As[lkc + 3][lrow] = av.w;
        Bs[lkc + 0][lrow] = wv.x; Bs[lkc + 1][lrow] = wv.y;
        Bs[lkc + 2][lrow] = wv.z; Bs[lkc + 3][lrow] = wv.w;
        __syncthreads();
#pragma unroll
        for (int k = 0; k < BK; ++k) {
            float4 a4 = *reinterpret_cast<const float4*>(&As[k][trow * 4]);
            float4 b4 = *reinterpret_cast<const float4*>(&Bs[k][tcol * 4]);
            float aR[4] = {a4.x, a4.y, a4.z, a4.w};
            float bR[4] = {b4.x, b4.y, b4.z, b4.w};
#pragma unroll
            for (int i = 0; i < 4; ++i)
#pragma unroll
                for (int j = 0; j < 4; ++j)
                    acc[i][j] = fmaf(aR[i], bR[j], acc[i][j]);
        }
        __syncthreads();
    }
#pragma unroll
    for (int i = 0; i < 4; ++i) {
        float4* dst = reinterpret_cast<float4*>(&C[(size_t)(bm + trow * 4 + i) * D_MODEL + bn + tcol * 4]);
        *dst = make_float4(acc[i][0], acc[i][1], acc[i][2], acc[i][3]);
    }
}

__global__ __launch_bounds__(256) void gemm_qkv_kernel(
    const float* __restrict__ A,
    const float* __restrict__ Wq, const float* __restrict__ Wk,
    const float* __restrict__ Wv, int M)
{
    int gn    = blockIdx.y * BN;            // [0,1536)
    int which = gn >> 9;                    // 0:Q 1:K 2:V
    int bn    = gn & 511;
    const float* W = (which == 0) ? Wq : (which == 1) ? Wk : Wv;
    float* C = g_QKV + (size_t)which * M * D_MODEL;
    gemm_body(A, W, C, blockIdx.x * BM, bn);
}

__global__ __launch_bounds__(256) void gemm_o_kernel(
    const float* __restrict__ Wo, float* __restrict__ Cout, int M)
{
    gemm_body(g_att, Wo, Cout, blockIdx.x * BM, blockIdx.y * BN);
}

// ---------------- LSH hashes ----------------
__global__ __launch_bounds__(256) void hash_kernel(const float* __restrict__ rv, int M)
{
    __shared__ float rs[HEADS * HDIM];
    for (int i = threadIdx.x; i < HEADS * HDIM; i += blockDim.x) rs[i] = rv[i];
    __syncthreads();

    int idx = blockIdx.x * blockDim.x + threadIdx.x;
    int total = 2 * M * HEADS;
    if (idx >= total) return;
    int isK = (idx >= M * HEADS) ? 1 : 0;
    int r = idx - isK * M * HEADS;
    int row = r >> 3;        // 0..M-1 (= b*1024+n)
    int h   = r & 7;

    const float4* src4 = reinterpret_cast<const float4*>(
        g_QKV + (size_t)isK * M * D_MODEL + (size_t)row * D_MODEL + h * HDIM);
    float dacc[8] = {};
#pragma unroll
    for (int c4 = 0; c4 < HDIM / 4; ++c4) {
        float4 xv = src4[c4];
#pragma unroll
        for (int k = 0; k < 8; ++k) {
            const float* rk = &rs[k * HDIM + c4 * 4];
            dacc[k] = fmaf(xv.x, rk[0], dacc[k]);
            dacc[k] = fmaf(xv.y, rk[1], dacc[k]);
            dacc[k] = fmaf(xv.z, rk[2], dacc[k]);
            dacc[k] = fmaf(xv.w, rk[3], dacc[k]);
        }
    }
    unsigned int bits = 0;
#pragma unroll
    for (int k = 0; k < 8; ++k) bits |= (dacc[k] >= 0.f ? 1u : 0u) << k;
    int bhn = ((row >> 10) * HEADS + h) * NSEQ + (row & (NSEQ - 1));
    (isK ? g_kh : g_qh)[bhn] = (unsigned char)bits;
}

// ---------------- sparse hyperbolic attention: one block per (b,h,n) ----------------
__global__ __launch_bounds__(128) void attn_kernel(int M)
{
    const int T = 128;
    const int PER = NSEQ / T;            // 8 contiguous j per thread
    int gid = blockIdx.x;                // bh*1024 + n
    int n  = gid & (NSEQ - 1);
    int bh = gid >> 10;
    int h = bh & 7, b = bh >> 3;

    const float* Q = g_QKV;
    const float* K = g_QKV + (size_t)M * D_MODEL;
    const float* V = g_QKV + 2 * (size_t)M * D_MODEL;

    __shared__ float qs[HDIM];
    __shared__ float sc[TOPK];
    __shared__ short selj[TOPK];
    __shared__ int hist[9];
    __shared__ int wsum_gt[4], wsum_eq[4];
    __shared__ int s_t, s_need;
    __shared__ float s_qn, s_mx, s_sum;
    __shared__ float red[4];
    __shared__ float obuf[HDIM];

    int tid = threadIdx.x, lane = tid & 31, warp = tid >> 5;
    size_t qoff = ((size_t)(b * NSEQ + n)) * D_MODEL + h * HDIM;
    if (tid < HDIM) qs[tid] = Q[qoff + tid];
    if (tid < 9) hist[tid] = 0;
    __syncthreads();

    // --- hash match counts for my 8 contiguous keys (register-resident) ---
    unsigned int qb = g_qh[bh * NSEQ + n];
    const unsigned char* khb = g_kh + bh * NSEQ;
    int base = tid * PER;
    uint2 kv8 = *reinterpret_cast<const uint2*>(khb + base);  // 8 bytes, aligned
    int m[PER];
#pragma unroll
    for (int i = 0; i < PER; ++i) {
        unsigned int byte = ((i < 4 ? kv8.x >> (8 * i) : kv8.y >> (8 * (i - 4))) & 0xFFu);
        m[i] = 8 - __popc(byte ^ qb);
    }

    // --- histogram: per-thread count per bucket, warp-reduce, 1 atomic/warp ---
#pragma unroll
    for (int v = 0; v < 9; ++v) {
        int c = 0;
#pragma unroll
        for (int i = 0; i < PER; ++i) c += (m[i] == v);
        c = __reduce_add_sync(0xffffffffu, c);
        if (lane == 0 && c) atomicAdd(&hist[v], c);
    }

    // q norm (warp 0)
    if (tid < 32) {
        float v = qs[tid] * qs[tid] + qs[tid + 32] * qs[tid + 32];
#pragma unroll
        for (int o = 16; o > 0; o >>= 1) v += __shfl_xor_sync(0xffffffffu, v, o);
        if (tid == 0) s_qn = v;
    }
    __syncthreads();

    if (tid == 0) {
        int cum = 0, t = 0, need = TOPK;
        for (int v = 8; v >= 0; --v) {
            if (cum + hist[v] >= TOPK) { t = v; need = TOPK - cum; break; }
            cum += hist[v];
        }
        s_t = t; s_need = need;
    }
    __syncthreads();
    int t = s_t, need = s_need, ngt = TOPK - need;

    // --- deterministic selection positions via two shuffle scans ---
    int cgt = 0, ceq = 0;
#pragma unroll
    for (int i = 0; i < PER; ++i) { cgt += (m[i] > t); ceq += (m[i] == t); }
    int sgt = cgt, seq = ceq;
#pragma unroll
    for (int o = 1; o < 32; o <<= 1) {
        int a = __shfl_up_sync(0xffffffffu, sgt, o); if (lane >= o) sgt += a;
        int e = __shfl_up_sync(0xffffffffu, seq, o); if (lane >= o) seq += e;
    }
    if (lane == 31) { wsum_gt[warp] = sgt; wsum_eq[warp] = seq; }
    __syncthreads();
    int rgt = sgt - cgt, req = seq - ceq;
#pragma unroll
    for (int w = 0; w < 4; ++w) {
        if (w < warp) { rgt += wsum_gt[w]; req += wsum_eq[w]; }
    }
#pragma unroll
    for (int i = 0; i < PER; ++i) {
        int j = base + i;
        if (m[i] > t) selj[rgt++] = (short)j;
        else if (m[i] == t) { if (req < need) selj[ngt + req] = (short)j; req++; }
    }
    __syncthreads();

    // --- Poincare distances for the selected keys ---
    float qn = s_qn;
    if (tid < TOPK) {
        int j = selj[tid];
        const float* kr = K + ((size_t)(b * NSEQ + j)) * D_MODEL + h * HDIM;
        float dsq = 0.f, kn = 0.f;
#pragma unroll
        for (int d0 = 0; d0 < HDIM; d0 += 4) {
            float4 kv = *reinterpret_cast<const float4*>(kr + d0);
            float dx = qs[d0 + 0] - kv.x, dy = qs[d0 + 1] - kv.y;
            float dz = qs[d0 + 2] - kv.z, dw = qs[d0 + 3] - kv.w;
            dsq += dx * dx + dy * dy + dz * dz + dw * dw;
            kn  += kv.x * kv.x + kv.y * kv.y + kv.z * kv.z + kv.w * kv.w;
        }
        float denom = fmaxf((1.f - qn) * (1.f - kn), 1e-6f);
        float ca = fmaxf(1.f + 2.f * dsq / denom, 1.f);
        sc[tid] = -acoshf(ca);
    }
    __syncthreads();

    // --- softmax over TOPK scores ---
    {
        float v = (tid < TOPK) ? sc[tid] : -3.4e38f;
#pragma unroll
        for (int o = 16; o > 0; o >>= 1) v = fmaxf(v, __shfl_xor_sync(0xffffffffu, v, o));
        if (lane == 0) red[warp] = v;
        __syncthreads();
        if (tid == 0) s_mx = fmaxf(fmaxf(red[0], red[1]), fmaxf(red[2], red[3]));
        __syncthreads();
        float e = (tid < TOPK) ? expf(sc[tid] - s_mx) : 0.f;
        if (tid < TOPK) sc[tid] = e;
        float sv = e;
#pragma unroll
        for (int o = 16; o > 0; o >>= 1) sv += __shfl_xor_sync(0xffffffffu, sv, o);
        if (lane == 0) red[warp] = sv;
        __syncthreads();
        if (tid == 0) s_sum = red[0] + red[1] + red[2] + red[3];
        __syncthreads();
    }
    float inv = 1.f / s_sum;

    // --- weighted V sum: two thread-halves split the s-range ---
    int d = tid & (HDIM - 1);
    int half = tid >> 6;
    float acc = 0.f;
    int s0 = half ? 51 : 0;
    int s1 = half ? TOPK : 51;
#pragma unroll 4
    for (int s = s0; s < s1; ++s) {
        int j = selj[s];
        acc += sc[s] * V[((size_t)(b * NSEQ + j)) * D_MODEL + h * HDIM + d];
    }
    if (half == 0) obuf[d] = acc;
    __syncthreads();
    if (half == 1)
        g_att[((size_t)(b * NSEQ + n)) * D_MODEL + h * HDIM + d] = (obuf[d] + acc) * inv;
}

// ---------------- entry ----------------
extern "C" void kernel_launch(void* const* d_in, const int* in_sizes, int n_in,
                              void* d_out, int out_size)
{
    const float* x  = (const float*)d_in[0];
    const float* Wq = (const float*)d_in[1];
    const float* Wk = (const float*)d_in[2];
    const float* Wv = (const float*)d_in[3];
    const float* Wo = (const float*)d_in[4];
    const float* rv = (const float*)d_in[5];
    float* out = (float*)d_out;

    int M = in_sizes[0] / D_MODEL;   // B*N = 2048

    dim3 gq(M / BM, (3 * D_MODEL) / BN);      // (32, 24) = 768 blocks
    gemm_qkv_kernel<<<gq, 256>>>(x, Wq, Wk, Wv, M);

    int hthreads = 2 * M * HEADS;             // 32768
    hash_kernel<<<(hthreads + 255) / 256, 256>>>(rv, M);

    attn_kernel<<<M * HEADS, 128>>>(M);       // 16384 blocks

    dim3 go(M / BM, D_MODEL / BN);            // (32, 8) = 256 blocks
    gemm_o_kernel<<<go, 256>>>(Wo, out, M);
}